// round 8
// baseline (speedup 1.0000x reference)
#include <cuda_runtime.h>
#include <math.h>
#include <float.h>

#define A_N 33600
#define G_N 256
#define C_N 80
#define TOPK 10
#define NT   512
#define GPB  2            // GTs per block
#define CAP  2048         // max inside anchors per GT (max box ~208x208 -> ~900 expected)
#define SENT 0xFFFFFFFFFFFFFFFFULL

// Scratch (allocation-free: __device__ globals)
__device__ float g_total_neg[A_N];
__device__ int   g_assigned[A_N];

// monotone float -> uint mapping, packed with index: lexicographic (cost asc, idx asc)
__device__ __forceinline__ unsigned long long packKey(float v, unsigned idx) {
    unsigned u = __float_as_uint(v);
    u = (u & 0x80000000u) ? ~u : (u | 0x80000000u);
    return (((unsigned long long)u) << 32) | (unsigned long long)idx;
}

// softplus difference with the reference's rounding sequence (rare path, keep exact)
__device__ __forceinline__ float sp_diff(float s) {
    float l = log1pf(expf(-fabsf(s)));
    return (fmaxf(-s, 0.0f) + l) - (fmaxf(s, 0.0f) + l);
}

// ---- kernel 1: prep = total_neg per anchor + init assigned + zero scores ----
__global__ void prep_kernel(const float* __restrict__ scores, float* __restrict__ out) {
    int idx = blockIdx.x * blockDim.x + threadIdx.x;
    if (idx < A_N) g_assigned[idx] = -1;
    const int n4 = (A_N * (C_N + 1)) / 4;   // 680400 float4s in the scores region
    if (idx < n4)
        ((float4*)(out + (size_t)5 * A_N))[idx] = make_float4(0.f, 0.f, 0.f, 0.f);
    int warp = idx >> 5, lane = idx & 31;
    if (warp >= A_N) return;
    float sum = 0.0f;
    for (int c = lane; c < C_N; c += 32) {
        float x = scores[warp * C_N + c];
        // fast softplus: max(x,0) + log(1 + exp(-|x|)); arg of log in (1,2]
        sum += fmaxf(x, 0.0f) + __logf(1.0f + __expf(-fabsf(x)));
    }
    for (int o = 16; o; o >>= 1) sum += __shfl_down_sync(0xffffffffu, sum, o);
    if (lane == 0) g_total_neg[warp] = sum;
}

// ---- kernel 2: fused sweep(2 GTs) + inline cost + warp top-k + scatter ----
__global__ __launch_bounds__(NT) void topk_kernel(
    const float* __restrict__ pred_scores,
    const float* __restrict__ pred_bboxes,
    const float* __restrict__ anchor_points,
    const int*   __restrict__ gt_labels,
    const float* __restrict__ gt_bboxes)
{
    const int g0  = blockIdx.x * GPB;
    const int tid = threadIdx.x;
    const int lane = tid & 31, wid = tid >> 5;

    __shared__ unsigned long long skeys[GPB][CAP];
    __shared__ int s_n[GPB];
    __shared__ int s_cnt[GPB];
    __shared__ unsigned long long swmin[NT / 32];

    if (tid < GPB) { s_n[tid] = 0; s_cnt[tid] = 0; }
    __syncthreads();

    // per-GT constants (both GTs in registers of every thread)
    float gx1[GPB], gy1[GPB], gx2[GPB], gy2[GPB], areag[GPB];
    int   lab[GPB];
#pragma unroll
    for (int gi = 0; gi < GPB; gi++) {
        float4 gb = ((const float4*)gt_bboxes)[g0 + gi];
        gx1[gi] = gb.x; gy1[gi] = gb.y; gx2[gi] = gb.z; gy2[gi] = gb.w;
        areag[gi] = (gb.z - gb.x) * (gb.w - gb.y);
        lab[gi] = gt_labels[g0 + gi];
    }

    const float2* ap2 = (const float2*)anchor_points;
    const float4* pb4 = (const float4*)pred_bboxes;

    // ---- sweep: inside test (inside == in_gt, radius 2.5 >= 0.5) + inline cost ----
    for (int a = tid; a < A_N; a += NT) {
        float2 ap = __ldg(ap2 + a);
        bool in0 = (ap.x >= gx1[0]) & (ap.x <= gx2[0]) & (ap.y >= gy1[0]) & (ap.y <= gy2[0]);
        bool in1 = (ap.x >= gx1[1]) & (ap.x <= gx2[1]) & (ap.y >= gy1[1]) & (ap.y <= gy2[1]);
        if (in0 | in1) {
            float4 pb = __ldg(pb4 + a);
            float area_p = (pb.z - pb.x) * (pb.w - pb.y);
#pragma unroll
            for (int gi = 0; gi < GPB; gi++) {
                bool in = gi ? in1 : in0;
                if (in) {
                    float w  = fmaxf(fminf(pb.z, gx2[gi]) - fmaxf(pb.x, gx1[gi]), 0.0f);
                    float h  = fmaxf(fminf(pb.w, gy2[gi]) - fmaxf(pb.y, gy1[gi]), 0.0f);
                    float ov = w * h;
                    if (ov > 0.0f) atomicAdd(&s_cnt[gi], 1);
                    float iou  = ov / (area_p + areag[gi] - ov + 1e-6f);
                    float iouc = -logf(fmaxf(iou, 1e-7f));
                    float s    = __ldg(pred_scores + (size_t)a * C_N + lab[gi]);
                    float cls  = g_total_neg[a] + sp_diff(s);
                    float cost = __fadd_rn(cls, __fmul_rn(3.0f, iouc));
                    int slot = atomicAdd(&s_n[gi], 1);
                    if (slot < CAP) skeys[gi][slot] = packKey(cost, (unsigned)a);
                }
            }
        }
    }
    __syncthreads();

    // ---- rare fallback: GT with zero inside anchors -> global argmin, dyn_k = 1 ----
#pragma unroll
    for (int gi = 0; gi < GPB; gi++) {
        if (s_n[gi] == 0) {   // uniform (smem, post-sync)
            unsigned long long best = SENT;
            for (int a = tid; a < A_N; a += NT) {
                float4 pb = __ldg(pb4 + a);
                float w  = fmaxf(fminf(pb.z, gx2[gi]) - fmaxf(pb.x, gx1[gi]), 0.0f);
                float h  = fmaxf(fminf(pb.w, gy2[gi]) - fmaxf(pb.y, gy1[gi]), 0.0f);
                float ov = w * h;
                float area_p = (pb.z - pb.x) * (pb.w - pb.y);
                float iou  = ov / (area_p + areag[gi] - ov + 1e-6f);
                float iouc = -logf(fmaxf(iou, 1e-7f));
                float s    = __ldg(pred_scores + (size_t)a * C_N + lab[gi]);
                float cls  = g_total_neg[a] + sp_diff(s);
                float cost = __fadd_rn(__fadd_rn(cls, __fmul_rn(3.0f, iouc)), 1e10f);
                unsigned long long k = packKey(cost, (unsigned)a);
                if (k < best) best = k;
            }
            for (int o = 16; o; o >>= 1) {
                unsigned long long oth = __shfl_down_sync(0xffffffffu, best, o);
                best = (oth < best) ? oth : best;
            }
            if (lane == 0) swmin[wid] = best;
            __syncthreads();
            if (tid == 0) {
                unsigned long long w = swmin[0];
                for (int i = 1; i < NT / 32; i++) if (swmin[i] < w) w = swmin[i];
                atomicMax(&g_assigned[(int)(w & 0xffffffffu)], g0 + gi);
            }
            __syncthreads();
        }
    }

    // ---- selection: warp gi handles GT g0+gi (no block syncs needed) ----
    if (wid < GPB) {
        const int gi = wid;
        const int n = min(s_n[gi], CAP);
        if (n > 0) {
            int cnt = s_cnt[gi];
            int k = (cnt < 1) ? 1 : ((cnt > TOPK) ? TOPK : cnt);
            // dyn_k <= cnt <= n, and every inside cost < every outside cost,
            // so the global top-dyn_k are exactly among these candidates.
            unsigned long long loc[TOPK];
#pragma unroll
            for (int j = 0; j < TOPK; j++) loc[j] = SENT;
            for (int i = lane; i < n; i += 32) {
                unsigned long long v = skeys[gi][i];
                if (v < loc[TOPK - 1]) {
                    loc[TOPK - 1] = v;
#pragma unroll
                    for (int j = TOPK - 1; j > 0; j--) {
                        bool sw = loc[j] < loc[j - 1];
                        unsigned long long lo = sw ? loc[j] : loc[j - 1];
                        unsigned long long hi = sw ? loc[j - 1] : loc[j];
                        loc[j - 1] = lo; loc[j] = hi;
                    }
                }
            }
            int p = 0;
            for (int r = 0; r < k; r++) {
                unsigned long long cand = (p < TOPK) ? loc[p] : SENT;
                unsigned long long m = cand;
#pragma unroll
                for (int o = 16; o; o >>= 1) {
                    unsigned long long oth = __shfl_xor_sync(0xffffffffu, m, o);
                    m = (oth < m) ? oth : m;
                }
                if (lane == 0) atomicMax(&g_assigned[(int)(m & 0xffffffffu)], g0 + gi);
                if (cand == m) p++;
            }
        }
    }
}

// ---- kernel 3: labels + bboxes + one-hot scatter (scores pre-zeroed) ----
__global__ void finalize_kernel(const float* __restrict__ pred_bboxes,
                                const int*   __restrict__ gt_labels,
                                const float* __restrict__ gt_bboxes,
                                float* __restrict__ out)
{
    int a = blockIdx.x * blockDim.x + threadIdx.x;
    if (a >= A_N) return;

    int  g    = g_assigned[a];
    bool pos  = (g >= 0);
    int  safe = pos ? g : 0;
    int  label = pos ? gt_labels[safe] : C_N;

    float4 gbx = ((const float4*)gt_bboxes)[safe];

    out[a] = (float)label;

    float4* ob = (float4*)(out + A_N);
    ob[a] = pos ? gbx : make_float4(0.f, 0.f, 0.f, 0.f);

    if (pos) {
        float4 pb = ((const float4*)pred_bboxes)[a];
        float w = fmaxf(fminf(pb.z, gbx.z) - fmaxf(pb.x, gbx.x), 0.0f);
        float h = fmaxf(fminf(pb.w, gbx.w) - fmaxf(pb.y, gbx.y), 0.0f);
        float ov = w * h;
        float area_p = (pb.z - pb.x) * (pb.w - pb.y);
        float area_g = (gbx.z - gbx.x) * (gbx.w - gbx.y);
        float iou = ov / (area_p + area_g - ov + 1e-6f);
        out[(size_t)5 * A_N + (size_t)a * (C_N + 1) + label] = iou;
    }
}

extern "C" void kernel_launch(void* const* d_in, const int* in_sizes, int n_in,
                              void* d_out, int out_size) {
    const float* pred_scores   = (const float*)d_in[0];
    const float* pred_bboxes   = (const float*)d_in[1];
    const float* anchor_points = (const float*)d_in[2];
    const int*   gt_labels     = (const int*)  d_in[3];
    const float* gt_bboxes     = (const float*)d_in[4];
    float* out = (float*)d_out;

    prep_kernel<<<(A_N * 32 + 255) / 256, 256>>>(pred_scores, out);
    topk_kernel<<<G_N / GPB, NT>>>(pred_scores, pred_bboxes, anchor_points,
                                   gt_labels, gt_bboxes);
    finalize_kernel<<<(A_N + 255) / 256, 256>>>(pred_bboxes, gt_labels, gt_bboxes, out);
}

// round 9
// speedup vs baseline: 2.3636x; 2.3636x over previous
#include <cuda_runtime.h>
#include <math.h>
#include <float.h>

#define A_N 33600
#define G_N 256
#define C_N 80
#define TOPK 10
#define NT   512
#define CAP  4096
#define SENT 0xFFFFFFFFFFFFFFFFULL

// Scratch (allocation-free: __device__ globals)
__device__ float g_total_neg[A_N];
__device__ int   g_assigned[A_N];

// monotone float -> uint mapping, packed with index: lexicographic (cost asc, idx asc)
__device__ __forceinline__ unsigned long long packKey(float v, unsigned idx) {
    unsigned u = __float_as_uint(v);
    u = (u & 0x80000000u) ? ~u : (u | 0x80000000u);
    return (((unsigned long long)u) << 32) | (unsigned long long)idx;
}

// softplus difference with the reference's rounding sequence
__device__ __forceinline__ float sp_diff(float s) {
    float l = log1pf(expf(-fabsf(s)));
    return (fmaxf(-s, 0.0f) + l) - (fmaxf(s, 0.0f) + l);
}

// ---- kernel 1: prep = total_neg per anchor + init assigned + zero scores ----
__global__ void prep_kernel(const float* __restrict__ scores, float* __restrict__ out) {
    int idx = blockIdx.x * blockDim.x + threadIdx.x;
    if (idx < A_N) g_assigned[idx] = -1;
    const int n4 = (A_N * (C_N + 1)) / 4;   // 680400 float4s in the scores region
    if (idx < n4)
        ((float4*)(out + (size_t)5 * A_N))[idx] = make_float4(0.f, 0.f, 0.f, 0.f);
    int warp = idx >> 5, lane = idx & 31;
    if (warp >= A_N) return;
    float sum = 0.0f;
    for (int c = lane; c < C_N; c += 32) {
        float x = scores[warp * C_N + c];
        // fast softplus: max(x,0) + log(1 + exp(-|x|)); arg of log in (1,2]
        sum += fmaxf(x, 0.0f) + __logf(1.0f + __expf(-fabsf(x)));
    }
    for (int o = 16; o; o >>= 1) sum += __shfl_down_sync(0xffffffffu, sum, o);
    if (lane == 0) g_total_neg[warp] = sum;
}

// ---- kernel 2: per-GT compact scan -> dense cost -> warp top-k -> scatter ----
__global__ __launch_bounds__(NT) void topk_kernel(
    const float* __restrict__ pred_scores,
    const float* __restrict__ pred_bboxes,
    const float* __restrict__ anchor_points,
    const int*   __restrict__ gt_labels,
    const float* __restrict__ gt_bboxes)
{
    const int g   = blockIdx.x;
    const int tid = threadIdx.x;
    const int lane = tid & 31, wid = tid >> 5;

    const float4 gb = ((const float4*)gt_bboxes)[g];
    const float gx1 = gb.x, gy1 = gb.y, gx2 = gb.z, gy2 = gb.w;
    const int   L   = gt_labels[g];
    const float area_g = (gx2 - gx1) * (gy2 - gy1);

    const float2* ap2 = (const float2*)anchor_points;
    const float4* pb4 = (const float4*)pred_bboxes;

    __shared__ int s_list[CAP];
    __shared__ unsigned long long s_keys[CAP];
    __shared__ unsigned long long swmin[NT / 32];
    __shared__ int s_n;
    __shared__ int s_cnt;

    if (tid == 0) { s_n = 0; s_cnt = 0; }
    __syncthreads();

    // ---- phase 1: cheap inside scan (inside == in_gt since radius 2.5 >= 0.5) ----
    for (int a = tid; a < A_N; a += NT) {
        float2 ap = __ldg(ap2 + a);
        if (ap.x >= gx1 && ap.x <= gx2 && ap.y >= gy1 && ap.y <= gy2) {
            int slot = atomicAdd(&s_n, 1);
            if (slot < CAP) s_list[slot] = a;
        }
    }
    __syncthreads();
    const int n = min(s_n, CAP);

    if (n > 0) {
        // ---- phase 2: dense cost over compacted candidates (mask = 0 inside) ----
        for (int i = tid; i < n; i += NT) {
            int a = s_list[i];
            float4 pb = __ldg(pb4 + a);
            float w  = fmaxf(fminf(pb.z, gx2) - fmaxf(pb.x, gx1), 0.0f);
            float h  = fmaxf(fminf(pb.w, gy2) - fmaxf(pb.y, gy1), 0.0f);
            float ov = w * h;
            if (ov > 0.0f) atomicAdd(&s_cnt, 1);
            float area_p = (pb.z - pb.x) * (pb.w - pb.y);
            float iou  = ov / (area_p + area_g - ov + 1e-6f);
            float iouc = -logf(fmaxf(iou, 1e-7f));
            float s    = __ldg(pred_scores + (size_t)a * C_N + L);
            float cls  = g_total_neg[a] + sp_diff(s);
            float cost = __fadd_rn(cls, __fmul_rn(3.0f, iouc));
            s_keys[i] = packKey(cost, (unsigned)a);
        }
        __syncthreads();

        // ---- phase 3: single-warp exact top-dyn_k selection + scatter ----
        if (wid == 0) {
            int cnt = s_cnt;
            int k = (cnt < 1) ? 1 : ((cnt > TOPK) ? TOPK : cnt);
            // dyn_k <= cnt <= n, and every inside cost < every outside cost,
            // so the global top-dyn_k are exactly among these candidates.
            unsigned long long loc[TOPK];
#pragma unroll
            for (int j = 0; j < TOPK; j++) loc[j] = SENT;
            for (int i = lane; i < n; i += 32) {
                unsigned long long v = s_keys[i];
                if (v < loc[TOPK - 1]) {
                    loc[TOPK - 1] = v;
#pragma unroll
                    for (int j = TOPK - 1; j > 0; j--) {
                        bool sw = loc[j] < loc[j - 1];
                        unsigned long long lo = sw ? loc[j] : loc[j - 1];
                        unsigned long long hi = sw ? loc[j - 1] : loc[j];
                        loc[j - 1] = lo; loc[j] = hi;
                    }
                }
            }
            int p = 0;
            for (int r = 0; r < k; r++) {
                unsigned long long cand = (p < TOPK) ? loc[p] : SENT;
                unsigned long long m = cand;
#pragma unroll
                for (int o = 16; o; o >>= 1) {
                    unsigned long long oth = __shfl_xor_sync(0xffffffffu, m, o);
                    m = (oth < m) ? oth : m;
                }
                if (lane == 0) atomicMax(&g_assigned[(int)(m & 0xffffffffu)], g);
                if (cand == m) p++;
            }
        }
    } else {
        // ---- zero inside anchors: dyn_k = 1, global argmin (all outside) ----
        unsigned long long best = SENT;
        for (int a = tid; a < A_N; a += NT) {
            float4 pb = __ldg(pb4 + a);
            float w  = fmaxf(fminf(pb.z, gx2) - fmaxf(pb.x, gx1), 0.0f);
            float h  = fmaxf(fminf(pb.w, gy2) - fmaxf(pb.y, gy1), 0.0f);
            float ov = w * h;
            float area_p = (pb.z - pb.x) * (pb.w - pb.y);
            float iou  = ov / (area_p + area_g - ov + 1e-6f);
            float iouc = -logf(fmaxf(iou, 1e-7f));
            float s    = __ldg(pred_scores + (size_t)a * C_N + L);
            float cls  = g_total_neg[a] + sp_diff(s);
            float cost = __fadd_rn(__fadd_rn(cls, __fmul_rn(3.0f, iouc)), 1e10f);
            unsigned long long k = packKey(cost, (unsigned)a);
            if (k < best) best = k;
        }
        for (int o = 16; o; o >>= 1) {
            unsigned long long oth = __shfl_down_sync(0xffffffffu, best, o);
            best = (oth < best) ? oth : best;
        }
        if (lane == 0) swmin[wid] = best;
        __syncthreads();
        if (tid == 0) {
            unsigned long long w = swmin[0];
            for (int i = 1; i < NT / 32; i++) if (swmin[i] < w) w = swmin[i];
            atomicMax(&g_assigned[(int)(w & 0xffffffffu)], g);
        }
    }
}

// ---- kernel 3: labels + bboxes + one-hot scatter (scores pre-zeroed) ----
__global__ void finalize_kernel(const float* __restrict__ pred_bboxes,
                                const int*   __restrict__ gt_labels,
                                const float* __restrict__ gt_bboxes,
                                float* __restrict__ out)
{
    int a = blockIdx.x * blockDim.x + threadIdx.x;
    if (a >= A_N) return;

    int  g    = g_assigned[a];
    bool pos  = (g >= 0);
    int  safe = pos ? g : 0;
    int  label = pos ? gt_labels[safe] : C_N;

    float4 gbx = ((const float4*)gt_bboxes)[safe];

    out[a] = (float)label;

    float4* ob = (float4*)(out + A_N);
    ob[a] = pos ? gbx : make_float4(0.f, 0.f, 0.f, 0.f);

    if (pos) {
        float4 pb = ((const float4*)pred_bboxes)[a];
        float w = fmaxf(fminf(pb.z, gbx.z) - fmaxf(pb.x, gbx.x), 0.0f);
        float h = fmaxf(fminf(pb.w, gbx.w) - fmaxf(pb.y, gbx.y), 0.0f);
        float ov = w * h;
        float area_p = (pb.z - pb.x) * (pb.w - pb.y);
        float area_g = (gbx.z - gbx.x) * (gbx.w - gbx.y);
        float iou = ov / (area_p + area_g - ov + 1e-6f);
        out[(size_t)5 * A_N + (size_t)a * (C_N + 1) + label] = iou;
    }
}

extern "C" void kernel_launch(void* const* d_in, const int* in_sizes, int n_in,
                              void* d_out, int out_size) {
    const float* pred_scores   = (const float*)d_in[0];
    const float* pred_bboxes   = (const float*)d_in[1];
    const float* anchor_points = (const float*)d_in[2];
    const int*   gt_labels     = (const int*)  d_in[3];
    const float* gt_bboxes     = (const float*)d_in[4];
    float* out = (float*)d_out;

    prep_kernel<<<(A_N * 32 + 255) / 256, 256>>>(pred_scores, out);
    topk_kernel<<<G_N, NT>>>(pred_scores, pred_bboxes, anchor_points,
                             gt_labels, gt_bboxes);
    finalize_kernel<<<(A_N + 255) / 256, 256>>>(pred_bboxes, gt_labels, gt_bboxes, out);
}